// round 3
// baseline (speedup 1.0000x reference)
#include <cuda_runtime.h>

// Problem constants
#define Bb 2
#define Ss 2048
#define Dd 1024
#define Hh 16
#define HD 64
#define Mm (Bb * Ss)   // 4096 rows

// Scratch (allocation-free rule: __device__ globals)
__device__ float g_q[Mm * Dd];
__device__ float g_k[Mm * Dd];
__device__ float g_v[Mm * Dd];
__device__ float g_attn[Mm * Dd];

// ---------------------------------------------------------------------------
// SGEMM body: C[M,N] = A[M,K] @ W[K,N] + bias,  M=4096 (per grid), N=K=1024.
// Block tile 128x128, BK=16, 256 threads, 8x8 per thread.
// ---------------------------------------------------------------------------
__device__ __forceinline__ void sgemm_body(const float* __restrict__ A,
                                           const float* __restrict__ W,
                                           const float* __restrict__ bias,
                                           float* __restrict__ C)
{
    __shared__ float As[16][128];   // transposed A tile: As[k][m]
    __shared__ float Bs[16][128];   // Bs[k][n]

    const int tid = threadIdx.x;
    const int tx = tid & 15;
    const int ty = tid >> 4;
    const int rowBase = blockIdx.y * 128;
    const int colBase = blockIdx.x * 128;

    float acc[8][8];
#pragma unroll
    for (int i = 0; i < 8; i++)
#pragma unroll
        for (int j = 0; j < 8; j++) acc[i][j] = 0.0f;

    for (int k0 = 0; k0 < Dd; k0 += 16) {
        // Load A tile (128x16) as float4, store transposed
#pragma unroll
        for (int i = 0; i < 2; i++) {
            int idx = tid + i * 256;          // 0..511
            int r   = idx >> 2;               // 0..127
            int c4  = (idx & 3) << 2;         // 0,4,8,12
            float4 a = *(const float4*)(A + (size_t)(rowBase + r) * Dd + k0 + c4);
            As[c4 + 0][r] = a.x;
            As[c4 + 1][r] = a.y;
            As[c4 + 2][r] = a.z;
            As[c4 + 3][r] = a.w;
        }
        // Load B tile (16x128) as float4 direct
#pragma unroll
        for (int i = 0; i < 2; i++) {
            int idx = tid + i * 256;
            int r   = idx >> 5;               // 0..15
            int c4  = (idx & 31) << 2;        // 0..124
            *(float4*)(&Bs[r][c4]) =
                *(const float4*)(W + (size_t)(k0 + r) * Dd + colBase + c4);
        }
        __syncthreads();

#pragma unroll
        for (int kk = 0; kk < 16; kk++) {
            float a[8], b[8];
            *(float4*)&a[0] = *(float4*)&As[kk][ty * 8];
            *(float4*)&a[4] = *(float4*)&As[kk][ty * 8 + 4];
            *(float4*)&b[0] = *(float4*)&Bs[kk][tx * 8];
            *(float4*)&b[4] = *(float4*)&Bs[kk][tx * 8 + 4];
#pragma unroll
            for (int i = 0; i < 8; i++)
#pragma unroll
                for (int j = 0; j < 8; j++)
                    acc[i][j] += a[i] * b[j];
        }
        __syncthreads();
    }

    // Epilogue: += bias, vectorized stores
#pragma unroll
    for (int i = 0; i < 8; i++) {
        size_t rowOff = (size_t)(rowBase + ty * 8 + i) * Dd;
#pragma unroll
        for (int j = 0; j < 8; j += 4) {
            int c = colBase + tx * 8 + j;
            float4 o;
            o.x = acc[i][j + 0] + bias[c + 0];
            o.y = acc[i][j + 1] + bias[c + 1];
            o.z = acc[i][j + 2] + bias[c + 2];
            o.w = acc[i][j + 3] + bias[c + 3];
            *(float4*)(C + rowOff + c) = o;
        }
    }
}

// Fused QKV projection: blockIdx.z selects which projection
__global__ __launch_bounds__(256)
void qkv_kernel(const float* __restrict__ x,
                const float* __restrict__ wq, const float* __restrict__ bq,
                const float* __restrict__ wk, const float* __restrict__ bk,
                const float* __restrict__ wv, const float* __restrict__ bv)
{
    const float* W;
    const float* bias;
    float* C;
    if (blockIdx.z == 0)      { W = wq; bias = bq; C = g_q; }
    else if (blockIdx.z == 1) { W = wk; bias = bk; C = g_k; }
    else                      { W = wv; bias = bv; C = g_v; }
    sgemm_body(x, W, bias, C);
}

// Output projection
__global__ __launch_bounds__(256)
void proj_kernel(const float* __restrict__ wo, const float* __restrict__ bo,
                 float* __restrict__ out)
{
    sgemm_body(g_attn, wo, bo, out);
}

// ---------------------------------------------------------------------------
// Flash attention, fp32. One block per (b, h, q-tile of 64 rows).
// 256 threads = 16x16 grid, 4x4 micro-tile each -> 64x64 tiles.
// Causal: iterate only k-tiles kt <= qt; mask only the diagonal tile.
// Smem: Qt[64][64] (d-major), KtPs[64][64] (K d-major, reused for P c-major),
//       Vs[64][64] -> exactly 48 KB static.
// ---------------------------------------------------------------------------
__global__ __launch_bounds__(256)
void attn_kernel()
{
    __shared__ float Qt[64 * 64];     // Qt[d*64 + r]
    __shared__ float KtPs[64 * 64];   // K phase: [d*64 + c]; P phase: [c*64 + r]
    __shared__ float Vs[64 * 64];     // Vs[c*64 + n]

    const int tid = threadIdx.x;
    const int tx = tid & 15;          // column group
    const int ty = tid >> 4;          // row group
    // Launch longest blocks (largest qt) first to reduce the tail
    const int qt = (Ss / 64 - 1) - blockIdx.x;
    const int b  = blockIdx.y >> 4;
    const int h  = blockIdx.y & 15;

    const size_t headOff = (size_t)b * Ss * Dd + (size_t)h * HD;
    const float* Qb = g_q + headOff;
    const float* Kb = g_k + headOff;
    const float* Vb = g_v + headOff;

    // Load Q tile transposed (d-major)
#pragma unroll
    for (int i = 0; i < 4; i++) {
        int idx = tid + i * 256;          // 0..1023
        int r   = idx >> 4;               // 0..63
        int d4  = (idx & 15) << 2;        // 0..60
        float4 q = *(const float4*)(Qb + (size_t)(qt * 64 + r) * Dd + d4);
        Qt[(d4 + 0) * 64 + r] = q.x;
        Qt[(d4 + 1) * 64 + r] = q.y;
        Qt[(d4 + 2) * 64 + r] = q.z;
        Qt[(d4 + 3) * 64 + r] = q.w;
    }

    float m[4], l[4], o[4][4];
#pragma unroll
    for (int i = 0; i < 4; i++) {
        m[i] = -1e30f;
        l[i] = 0.0f;
#pragma unroll
        for (int j = 0; j < 4; j++) o[i][j] = 0.0f;
    }

    for (int kt = 0; kt <= qt; kt++) {
        __syncthreads();  // prior-iter PV readers done; Qt visible on iter 0

        // Load K tile transposed + V tile direct
#pragma unroll
        for (int i = 0; i < 4; i++) {
            int idx = tid + i * 256;
            int c   = idx >> 4;
            int d4  = (idx & 15) << 2;
            float4 kq = *(const float4*)(Kb + (size_t)(kt * 64 + c) * Dd + d4);
            KtPs[(d4 + 0) * 64 + c] = kq.x;
            KtPs[(d4 + 1) * 64 + c] = kq.y;
            KtPs[(d4 + 2) * 64 + c] = kq.z;
            KtPs[(d4 + 3) * 64 + c] = kq.w;
            *(float4*)(Vs + c * 64 + d4) =
                *(const float4*)(Vb + (size_t)(kt * 64 + c) * Dd + d4);
        }
        __syncthreads();

        // S = Q K^T (4x4 micro-tile per thread)
        float s[4][4];
#pragma unroll
        for (int i = 0; i < 4; i++)
#pragma unroll
            for (int j = 0; j < 4; j++) s[i][j] = 0.0f;

#pragma unroll 8
        for (int d = 0; d < 64; d++) {
            float4 qa = *(const float4*)(Qt + d * 64 + ty * 4);
            float4 kv = *(const float4*)(KtPs + d * 64 + tx * 4);
            float av[4] = {qa.x, qa.y, qa.z, qa.w};
            float bv2[4] = {kv.x, kv.y, kv.z, kv.w};
#pragma unroll
            for (int i = 0; i < 4; i++)
#pragma unroll
                for (int j = 0; j < 4; j++)
                    s[i][j] += av[i] * bv2[j];
        }

        // Scale + causal mask (diagonal tile only) + local row max
        const bool diag = (kt == qt);
        float mloc[4];
#pragma unroll
        for (int i = 0; i < 4; i++) {
            mloc[i] = -1e30f;
#pragma unroll
            for (int j = 0; j < 4; j++) {
                float v = s[i][j] * 0.125f;            // 1/sqrt(64)
                if (diag && (tx * 4 + j) > (ty * 4 + i)) v -= 1e9f;  // mask * NEG
                s[i][j] = v;
                mloc[i] = fmaxf(mloc[i], v);
            }
        }
        // Reduce row max over the 16 lanes sharing a row group
#pragma unroll
        for (int i = 0; i < 4; i++) {
#pragma unroll
            for (int off = 8; off >= 1; off >>= 1)
                mloc[i] = fmaxf(mloc[i], __shfl_xor_sync(0xffffffffu, mloc[i], off));
        }

        // Online softmax update
        float psum[4];
#pragma unroll
        for (int i = 0; i < 4; i++) {
            float mnew = fmaxf(m[i], mloc[i]);
            float f = __expf(m[i] - mnew);
            m[i] = mnew;
            l[i] *= f;
#pragma unroll
            for (int j = 0; j < 4; j++) o[i][j] *= f;
            float ps = 0.0f;
#pragma unroll
            for (int j = 0; j < 4; j++) {
                float p = __expf(s[i][j] - mnew);
                s[i][j] = p;
                ps += p;
            }
            psum[i] = ps;
        }
#pragma unroll
        for (int i = 0; i < 4; i++) {
#pragma unroll
            for (int off = 8; off >= 1; off >>= 1)
                psum[i] += __shfl_xor_sync(0xffffffffu, psum[i], off);
            l[i] += psum[i];
        }

        __syncthreads();  // all K reads done before P overlays KtPs
        // Write P (c-major so PV can load float4 over r)
#pragma unroll
        for (int i = 0; i < 4; i++)
#pragma unroll
            for (int j = 0; j < 4; j++)
                KtPs[(tx * 4 + j) * 64 + (ty * 4 + i)] = s[i][j];
        __syncthreads();

        // O += P V
#pragma unroll 8
        for (int c = 0; c < 64; c++) {
            float4 pa = *(const float4*)(KtPs + c * 64 + ty * 4);
            float4 vv = *(const float4*)(Vs + c * 64 + tx * 4);
            float pv[4] = {pa.x, pa.y, pa.z, pa.w};
            float vb2[4] = {vv.x, vv.y, vv.z, vv.w};
#pragma unroll
            for (int i = 0; i < 4; i++)
#pragma unroll
                for (int j = 0; j < 4; j++)
                    o[i][j] += pv[i] * vb2[j];
        }
    }

    // Epilogue: normalize and store (merged-heads layout [B,S,D])
    float* Ob = g_attn + headOff;
#pragma unroll
    for (int i = 0; i < 4; i++) {
        float inv = 1.0f / l[i];
        int r = qt * 64 + ty * 4 + i;
        float4 ov;
        ov.x = o[i][0] * inv;
        ov.y = o[i][1] * inv;
        ov.z = o[i][2] * inv;
        ov.w = o[i][3] * inv;
        *(float4*)(Ob + (size_t)r * Dd + tx * 4) = ov;
    }
}

// ---------------------------------------------------------------------------
extern "C" void kernel_launch(void* const* d_in, const int* in_sizes, int n_in,
                              void* d_out, int out_size)
{
    (void)in_sizes; (void)n_in; (void)out_size;
    const float* x  = (const float*)d_in[0];
    // d_in[1] = mask: exactly triu(ones)*1 -> applied analytically (identical result)
    const float* wq = (const float*)d_in[2];
    const float* bq = (const float*)d_in[3];
    const float* wk = (const float*)d_in[4];
    const float* bk = (const float*)d_in[5];
    const float* wv = (const float*)d_in[6];
    const float* bv = (const float*)d_in[7];
    const float* wo = (const float*)d_in[8];
    const float* bo = (const float*)d_in[9];
    float* out = (float*)d_out;

    dim3 blk(256);

    dim3 gQKV(Dd / 128, Mm / 128, 3);
    qkv_kernel<<<gQKV, blk>>>(x, wq, bq, wk, bk, wv, bv);

    dim3 gAttn(Ss / 64, Bb * Hh);
    attn_kernel<<<gAttn, blk>>>();

    dim3 gProj(Dd / 128, Mm / 128, 1);
    proj_kernel<<<gProj, blk>>>(wo, bo, out);
}

// round 9
// speedup vs baseline: 2.9296x; 2.9296x over previous
#include <cuda_runtime.h>
#include <cuda_bf16.h>
#include <stdint.h>

typedef __nv_bfloat16 bf16;

// Problem constants
#define Bb 2
#define Ss 2048
#define Dd 1024
#define Hh 16
#define HD 64
#define Mm (Bb * Ss)   // 4096 rows
#define WS (Dd * Dd)

// Scratch (__device__ globals per allocation rules)
__device__ bf16 g_xh[Mm * Dd];
__device__ bf16 g_xl[Mm * Dd];
__device__ bf16 g_qh[Mm * Dd];
__device__ bf16 g_ql[Mm * Dd];
__device__ bf16 g_kh[Mm * Dd];
__device__ bf16 g_kl[Mm * Dd];
__device__ bf16 g_vh[Mm * Dd];
__device__ bf16 g_vl[Mm * Dd];
__device__ bf16 g_ah[Mm * Dd];
__device__ bf16 g_al[Mm * Dd];
__device__ bf16 g_wth[4 * WS];   // W^T [n][k] hi
__device__ bf16 g_wtl[4 * WS];   // W^T [n][k] lo

// ---------------------------------------------------------------------------
// Helpers (base sm_80+ ISA only: mma.sync / ldmatrix / cp.async)
// ---------------------------------------------------------------------------
__device__ __forceinline__ uint32_t smem_u32(const void* p) {
    uint32_t a;
    asm("{ .reg .u64 t; cvta.to.shared.u64 t, %1; cvt.u32.u64 %0, t; }"
        : "=r"(a) : "l"(p));
    return a;
}

__device__ __forceinline__ void ldsm4(uint32_t* r, uint32_t addr) {
    asm volatile("ldmatrix.sync.aligned.m8n8.x4.shared.b16 {%0,%1,%2,%3}, [%4];"
                 : "=r"(r[0]), "=r"(r[1]), "=r"(r[2]), "=r"(r[3]) : "r"(addr));
}
__device__ __forceinline__ void ldsm4t(uint32_t* r, uint32_t addr) {
    asm volatile("ldmatrix.sync.aligned.m8n8.x4.trans.shared.b16 {%0,%1,%2,%3}, [%4];"
                 : "=r"(r[0]), "=r"(r[1]), "=r"(r[2]), "=r"(r[3]) : "r"(addr));
}
__device__ __forceinline__ void mma16816(float* c, const uint32_t* a, const uint32_t* b) {
    asm volatile(
        "mma.sync.aligned.m16n8k16.row.col.f32.bf16.bf16.f32 "
        "{%0,%1,%2,%3}, {%4,%5,%6,%7}, {%8,%9}, {%0,%1,%2,%3};"
        : "+f"(c[0]), "+f"(c[1]), "+f"(c[2]), "+f"(c[3])
        : "r"(a[0]), "r"(a[1]), "r"(a[2]), "r"(a[3]), "r"(b[0]), "r"(b[1]));
}
__device__ __forceinline__ void cp16(uint32_t dst, const void* src) {
    asm volatile("cp.async.cg.shared.global [%0], [%1], 16;" :: "r"(dst), "l"(src));
}
#define CP_COMMIT asm volatile("cp.async.commit_group;")
#define CP_WAIT0  asm volatile("cp.async.wait_group 0;")
#define CP_WAIT1  asm volatile("cp.async.wait_group 1;")

// pack two fp32 -> bf16x2 (lo in low half)
__device__ __forceinline__ uint32_t pack2(float lo, float hi) {
    uint32_t d;
    asm("cvt.rn.bf16x2.f32 %0, %1, %2;" : "=r"(d) : "f"(hi), "f"(lo));
    return d;
}
__device__ __forceinline__ float bfround(float v) {
    return __bfloat162float(__float2bfloat16(v));
}
// swizzled byte offset within a [row][64 bf16] tile (128B rows)
__device__ __forceinline__ uint32_t swz(int row, int chunk) {
    return (uint32_t)(row * 128 + ((chunk ^ (row & 7)) << 4));
}

// ---------------------------------------------------------------------------
// Prep kernels
// ---------------------------------------------------------------------------
__global__ __launch_bounds__(256)
void split_x_kernel(const float4* __restrict__ src)
{
    int i = blockIdx.x * blockDim.x + threadIdx.x;   // over Mm*Dd/4
    float4 v = src[i];
    float h0 = bfround(v.x), h1 = bfround(v.y), h2 = bfround(v.z), h3 = bfround(v.w);
    uint32_t* dh = (uint32_t*)g_xh;
    uint32_t* dl = (uint32_t*)g_xl;
    dh[2 * i]     = pack2(h0, h1);
    dh[2 * i + 1] = pack2(h2, h3);
    dl[2 * i]     = pack2(v.x - h0, v.y - h1);
    dl[2 * i + 1] = pack2(v.z - h2, v.w - h3);
}

__global__ __launch_bounds__(256)
void trans_split_w_kernel(const float* __restrict__ wq, const float* __restrict__ wk,
                          const float* __restrict__ wv, const float* __restrict__ wo)
{
    __shared__ float t[32][33];
    int z = blockIdx.z;
    const float* W = (z == 0) ? wq : (z == 1) ? wk : (z == 2) ? wv : wo;
    bf16* oh = g_wth + (size_t)z * WS;
    bf16* ol = g_wtl + (size_t)z * WS;
    int n0 = blockIdx.x * 32, k0 = blockIdx.y * 32;
    int tx = threadIdx.x, ty = threadIdx.y;   // 32 x 8
#pragma unroll
    for (int i = 0; i < 4; i++)
        t[ty + 8 * i][tx] = W[(size_t)(k0 + ty + 8 * i) * Dd + n0 + tx];
    __syncthreads();
#pragma unroll
    for (int i = 0; i < 4; i++) {
        int n = n0 + ty + 8 * i;
        int k = k0 + tx;
        float v = t[tx][ty + 8 * i];
        float h = bfround(v);
        oh[(size_t)n * Dd + k] = __float2bfloat16(h);
        ol[(size_t)n * Dd + k] = __float2bfloat16(v - h);
    }
}

// ---------------------------------------------------------------------------
// HMMA split-bf16 GEMM: C[M=4096, N=1024] = A @ W + bias
// A hi/lo [M][K] row-major; B hi/lo = W^T [N][K] row-major.
// 128x128 block tile, K-chunk 64, 8 warps (64x32 warp tiles), cp.async 2-stage.
// mode 0: qkv (z selects), writes bf16 hi/lo.  mode 1: proj, writes fp32 Cf.
// ---------------------------------------------------------------------------
#define GSTAGE 65536   // Ah,Al,Bh,Bl tiles x 16KB
#define GSMEM  (2 * GSTAGE)

__device__ __forceinline__ void gemm_load_chunk(
    uint32_t dstStage, const bf16* Ah, const bf16* Al,
    const bf16* Bh, const bf16* Bl, int rowBase, int colBase, int k0, int tid)
{
#pragma unroll
    for (int buf = 0; buf < 4; buf++) {
        const bf16* sp = (buf == 0) ? Ah : (buf == 1) ? Al : (buf == 2) ? Bh : Bl;
        const int rb = (buf < 2) ? rowBase : colBase;
        uint32_t tb = dstStage + buf * 16384;
#pragma unroll
        for (int i = 0; i < 4; i++) {
            int idx = tid + i * 256;      // 0..1023
            int row = idx >> 3;
            int c = idx & 7;
            cp16(tb + swz(row, c), sp + (size_t)(rb + row) * Dd + k0 + c * 8);
        }
    }
}

__global__ __launch_bounds__(256)
void hmma_gemm(int mode, const float* __restrict__ bias0,
               const float* __restrict__ bias1, const float* __restrict__ bias2,
               float* __restrict__ Cf)
{
    extern __shared__ char sm[];
    const uint32_t sb = smem_u32(sm);

    const int tid = threadIdx.x;
    const int lane = tid & 31;
    const int wid = tid >> 5;
    const int z = blockIdx.z;
    const int rowBase = blockIdx.y * 128;
    const int colBase = blockIdx.x * 128;

    const bf16 *Ah, *Al, *Bh, *Bl;
    bf16 *Oh = nullptr, *Ol = nullptr;
    const float* bias;
    if (mode == 0) {
        Ah = g_xh; Al = g_xl;
        Bh = g_wth + (size_t)z * WS; Bl = g_wtl + (size_t)z * WS;
        bias = (z == 0) ? bias0 : (z == 1) ? bias1 : bias2;
        Oh = (z == 0) ? g_qh : (z == 1) ? g_kh : g_vh;
        Ol = (z == 0) ? g_ql : (z == 1) ? g_kl : g_vl;
    } else {
        Ah = g_ah; Al = g_al;
        Bh = g_wth + 3 * (size_t)WS; Bl = g_wtl + 3 * (size_t)WS;
        bias = bias0;
    }

    const int wr = (wid & 1) * 64;    // warp row offset within 128
    const int wc = (wid >> 1) * 32;   // warp col offset within 128
    const int lrow = lane & 15;
    const int lsel = lane >> 4;

    float acc[4][4][4];
#pragma unroll
    for (int a = 0; a < 4; a++)
#pragma unroll
        for (int b = 0; b < 4; b++)
#pragma unroll
            for (int c = 0; c < 4; c++) acc[a][b][c] = 0.0f;

    gemm_load_chunk(sb, Ah, Al, Bh, Bl, rowBase, colBase, 0, tid);
    CP_COMMIT;

    for (int ch = 0; ch < 16; ch++) {
        if (ch + 1 < 16) {
            gemm_load_chunk(sb + ((ch + 1) & 1) * GSTAGE, Ah, Al, Bh, Bl,
                            rowBase, colBase, (ch + 1) * 64, tid);
            CP_COMMIT;
            CP_WAIT1;
        } else {
            CP_WAIT0;
        }
        __syncthreads();

        const uint32_t st = sb + (ch & 1) * GSTAGE;
        const uint32_t sAh = st, sAl = st + 16384, sBh = st + 32768, sBl = st + 49152;
#pragma unroll
        for (int kk = 0; kk < 4; kk++) {
            uint32_t ah[4][4], al[4][4], bh[2][4], bl[2][4];
            const int half = kk * 2 + lsel;
#pragma unroll
            for (int mt = 0; mt < 4; mt++) {
                int row = wr + mt * 16 + lrow;
                uint32_t off = swz(row, half);
                ldsm4(ah[mt], sAh + off);
                ldsm4(al[mt], sAl + off);
            }
#pragma unroll
            for (int np = 0; np < 2; np++) {
                int n = wc + np * 16 + lrow;
                uint32_t off = swz(n, half);
                ldsm4(bh[np], sBh + off);
                ldsm4(bl[np], sBl + off);
            }
#pragma unroll
            for (int mt = 0; mt < 4; mt++) {
#pragma unroll
                for (int nt = 0; nt < 4; nt++) {
                    int np = nt >> 1, sub = nt & 1;
                    uint32_t bbh[2] = { bh[np][sub], bh[np][sub + 2] };
                    uint32_t bbl[2] = { bl[np][sub], bl[np][sub + 2] };
                    mma16816(acc[mt][nt], ah[mt], bbh);
                    mma16816(acc[mt][nt], ah[mt], bbl);
                    mma16816(acc[mt][nt], al[mt], bbh);
                }
            }
        }
        __syncthreads();
    }

    // Epilogue
#pragma unroll
    for (int mt = 0; mt < 4; mt++) {
        int r0 = rowBase + wr + mt * 16 + (lane >> 2);
        int r1 = r0 + 8;
#pragma unroll
        for (int nt = 0; nt < 4; nt++) {
            int cg = colBase + wc + nt * 8 + (lane & 3) * 2;
            float b0v = bias[cg], b1v = bias[cg + 1];
            float v0 = acc[mt][nt][0] + b0v;
            float v1 = acc[mt][nt][1] + b1v;
            float v2 = acc[mt][nt][2] + b0v;
            float v3 = acc[mt][nt][3] + b1v;
            if (mode == 1) {
                *(float2*)(Cf + (size_t)r0 * Dd + cg) = make_float2(v0, v1);
                *(float2*)(Cf + (size_t)r1 * Dd + cg) = make_float2(v2, v3);
            } else {
                float h0 = bfround(v0), h1 = bfround(v1);
                float h2 = bfround(v2), h3 = bfround(v3);
                *(uint32_t*)(Oh + (size_t)r0 * Dd + cg) = pack2(h0, h1);
                *(uint32_t*)(Oh + (size_t)r1 * Dd + cg) = pack2(h2, h3);
                *(uint32_t*)(Ol + (size_t)r0 * Dd + cg) = pack2(v0 - h0, v1 - h1);
                *(uint32_t*)(Ol + (size_t)r1 * Dd + cg) = pack2(v2 - h2, v3 - h3);
            }
        }
    }
}

// ---------------------------------------------------------------------------
// HMMA flash attention. q-tile 128 (8 warps x 16 rows), kv-tile 64, 2-stage.
// S = Qh Kh^T + Qh Kl^T + Ql Kh^T (fp32 frags); softmax in regs;
// P split to bf16 hi/lo fed as A-frags; V via ldmatrix.trans.
// Smem: Qh 16K | Ql 16K | stage0 {Kh,Kl,Vh,Vl 8K each} | stage1 -> 96KB.
// ---------------------------------------------------------------------------
#define ASTAGE 32768
#define ASMEM  (32768 + 2 * ASTAGE)

__device__ __forceinline__ void attn_load_kv(uint32_t dst, int b, int h, int kt, int tid)
{
#pragma unroll
    for (int i = 0; i < 8; i++) {
        int idx = tid + i * 256;
        int t = idx >> 9;          // 0=Kh 1=Kl 2=Vh 3=Vl
        int w = idx & 511;
        int row = w >> 3, c = w & 7;
        const bf16* src = (t == 0) ? g_kh : (t == 1) ? g_kl : (t == 2) ? g_vh : g_vl;
        src += (size_t)(b * Ss + kt * 64 + row) * Dd + h * HD + c * 8;
        cp16(dst + t * 8192 + swz(row, c), src);
    }
}

__global__ __launch_bounds__(256)
void attn_hmma()
{
    extern __shared__ char sm[];
    const uint32_t sb = smem_u32(sm);

    const int tid = threadIdx.x;
    const int lane = tid & 31;
    const int wid = tid >> 5;
    const int qt = 15 - blockIdx.x;         // longest first
    const int b = blockIdx.y >> 4;
    const int h = blockIdx.y & 15;
    const int wr = wid * 16;
    const int lrow = lane & 15;
    const int lsel = lane >> 4;
    const int nkt = 2 * qt + 2;

    // Prologue: KV stage 0 + Q tiles (one cp.async group)
    attn_load_kv(sb + 32768, b, h, 0, tid);
#pragma unroll
    for (int i = 0; i < 8; i++) {
        int idx = tid + i * 256;
        int t = idx >> 10;                   // 0=Qh 1=Ql
        int w = idx & 1023;
        int row = w >> 3, c = w & 7;
        const bf16* src = (t == 0) ? g_qh : g_ql;
        src += (size_t)(b * Ss + qt * 128 + row) * Dd + h * HD + c * 8;
        cp16(sb + t * 16384 + swz(row, c), src);
    }
    CP_COMMIT;

    float o[8][4];
#pragma unroll
    for (int i = 0; i < 8; i++)
#pragma unroll
        for (int j = 0; j < 4; j++) o[i][j] = 0.0f;
    float m0 = -1e30f, m1 = -1e30f, l0 = 0.0f, l1 = 0.0f;

    const int rowA = qt * 128 + wr + (lane >> 2);   // this thread's row_lo (seq index)

    for (int kt = 0; kt < nkt; kt++) {
        if (kt + 1 < nkt) {
            attn_load_kv(sb + 32768 + ((kt + 1) & 1) * ASTAGE, b, h, kt + 1, tid);
            CP_COMMIT;
            CP_WAIT1;
        } else {
            CP_WAIT0;
        }
        __syncthreads();

        // Warp-level causal skip: this warp's rows are qt*128+wr .. +15
        if (kt * 64 <= qt * 128 + wr + 15) {
            const uint32_t st = sb + 32768 + (kt & 1) * ASTAGE;

            // --- S = Q K^T (3-term split) ---
            float sc[8][4];
#pragma unroll
            for (int i = 0; i < 8; i++)
#pragma unroll
                for (int j = 0; j < 4; j++) sc[i][j] = 0.0f;

#pragma unroll
            for (int kk = 0; kk < 4; kk++) {
                const int half = kk * 2 + lsel;
                uint32_t qh4[4], ql4[4];
                {
                    int row = wr + lrow;
                    uint32_t off = swz(row, half);
                    ldsm4(qh4, sb + off);
                    ldsm4(ql4, sb + 16384 + off);
                }
#pragma unroll
                for (int np = 0; np < 4; np++) {
                    uint32_t khf[4], klf[4];
                    int n = np * 16 + lrow;
                    uint32_t off = swz(n, half);
                    ldsm4(khf, st + off);
                    ldsm4(klf, st + 8192 + off);
#pragma unroll
                    for (int s2 = 0; s2 < 2; s2++) {
                        int nt = np * 2 + s2;
                        uint32_t bbh[2] = { khf[s2], khf[s2 + 2] };
                        uint32_t bbl[2] = { klf[s2], klf[s2 + 2] };
                        mma16816(sc[nt], qh4, bbh);
                        mma16816(sc[nt], qh4, bbl);
                        mma16816(sc[nt], ql4, bbh);
                    }
                }
            }

            // --- scale + causal mask + row max ---
            float mx0 = -1e30f, mx1 = -1e30f;
#pragma unroll
            for (int nt = 0; nt < 8; nt++) {
                int colb = kt * 64 + nt * 8 + (lane & 3) * 2;
#pragma unroll
                for (int j = 0; j < 4; j++) {
                    float v = sc[nt][j] * 0.125f;
                    int col = colb + (j & 1);
                    int row = rowA + (j >> 1) * 8;
                    if (col > row) v -= 1e9f;
                    sc[nt][j] = v;
                    if (j < 2) mx0 = fmaxf(mx0, v); else mx1 = fmaxf(mx1, v);
                }
            }
#pragma unroll
            for (int off = 1; off <= 2; off <<= 1) {
                mx0 = fmaxf(mx0, __shfl_xor_sync(0xffffffffu, mx0, off));
                mx1 = fmaxf(mx1, __shfl_xor_sync(0xffffffffu, mx1, off));
            }

            // --- online softmax update ---
            float mn0 = fmaxf(m0, mx0), mn1 = fmaxf(m1, mx1);
            float f0 = __expf(m0 - mn0), f1 = __expf(m1 - mn1);
            m0 = mn0; m1 = mn1;
            l0 *= f0; l1 *= f1;
#pragma unroll
            for (int nt = 0; nt < 8; nt++) {
                o[nt][0] *= f0; o[nt][1] *= f0;
                o[nt][2] *= f1; o[nt][3] *= f1;
            }
            float ps0 = 0.0f, ps1 = 0.0f;
#pragma unroll
            for (int nt = 0; nt < 8; nt++) {
                float p0 = __expf(sc[nt][0] - mn0);
                float p1 = __expf(sc[nt][1] - mn0);
                float p2 = __expf(sc[nt][2] - mn1);
                float p3 = __expf(sc[nt][3] - mn1);
                sc[nt][0] = p0; sc[nt][1] = p1; sc[nt][2] = p2; sc[nt][3] = p3;
                ps0 += p0 + p1; ps1 += p2 + p3;
            }
#pragma unroll
            for (int off = 1; off <= 2; off <<= 1) {
                ps0 += __shfl_xor_sync(0xffffffffu, ps0, off);
                ps1 += __shfl_xor_sync(0xffffffffu, ps1, off);
            }
            l0 += ps0; l1 += ps1;

            // --- P -> bf16 hi/lo A-fragments ---
            uint32_t aph[4][4], apl[4][4];
#pragma unroll
            for (int nt = 0; nt < 8; nt++) {
                int c = nt >> 1, i0 = (nt & 1) * 2;
                float p0 = sc[nt][0], p1 = sc[nt][1], p2 = sc[nt][2], p3 = sc[nt][3];
                float h0 = bfround(p0), h1 = bfround(p1);
                float h2 = bfround(p2), h3 = bfround(p3);
                aph[c][i0]     = pack2(h0, h1);
                aph[c][i0 + 1] = pack2(h2, h3);
                apl[c][i0]     = pack2(p0 - h0, p1 - h1);
                apl[c][i0 + 1] = pack2(p2 - h2, p3 - h3);
            }

            // --- O += P V (V via ldmatrix.trans) ---
#pragma unroll
            for (int c = 0; c < 4; c++) {
#pragma unroll
                for (int dp = 0; dp < 4; dp++) {
                    uint32_t vh4[4], vl4[4];
                    int row = c * 16 + lrow;
                    int half = dp * 2 + lsel;
                    uint32_t off = swz(row, half);
                    ldsm4t(vh4, st + 16384 + off);
                    ldsm4t(vl4, st + 24576 + off);
#pragma unroll
                    for (int s2 = 0; s2 < 2; s2++) {
                        int nt = dp * 2 + s2;
                        uint32_t bbh[2] = { vh4[s2 * 2], vh4[s2 * 2 + 1] };
                        uint32_t bbl[2] = { vl4[s2 * 2], vl4[s2 * 2 + 1] };
                        mma16816(o[nt], aph[c], bbh);
                        mma16816(o[nt], aph[c], bbl);
                        mma16816(o[nt], apl[c], bbh);
                    }
                }
            }
        }
        __syncthreads();
    }

    // Epilogue: normalize, write bf16 hi/lo of attention output
    float inv0 = 1.0f / l0, inv1 = 1.0f / l1;
    size_t r0 = (size_t)(b * Ss) + rowA;
    size_t r1 = r0 + 8;
#pragma unroll
    for (int nt = 0; nt < 8; nt++) {
        int col = h * HD + nt * 8 + (lane & 3) * 2;
        float v0 = o[nt][0] * inv0, v1 = o[nt][1] * inv0;
        float v2 = o[nt][2] * inv1, v3 = o[nt][3] * inv1;
        float h0 = bfround(v0), h1 = bfround(v1);
        float h2 = bfround(v2), h3 = bfround(v3);
        *(uint32_t*)(g_ah + r0 * Dd + col) = pack2(h0, h1);
        *(uint32_t*)(g_ah + r1 * Dd + col) = pack2(h2, h3);
        *(uint32_t*)(g_al + r0 * Dd + col) = pack2(v0 - h0, v1 - h1);
        *(uint32_t*)(g_al + r1 * Dd + col) = pack2(v2 - h2, v3 - h3);
    }
}

// ---------------------------------------------------------------------------
extern "C" void kernel_launch(void* const* d_in, const int* in_sizes, int n_in,
                              void* d_out, int out_size)
{
    (void)in_sizes; (void)n_in; (void)out_size;
    const float* x  = (const float*)d_in[0];
    // d_in[1] = mask: exactly triu(ones) -> applied analytically (identical result)
    const float* wq = (const float*)d_in[2];
    const float* bq = (const float*)d_in[3];
    const float* wk = (const float*)d_in[4];
    const float* bk = (const float*)d_in[5];
    const float* wv = (const float*)d_in[6];
    const float* bv = (const float*)d_in[7];
    const float* wo = (const float*)d_in[8];
    const float* bo = (const float*)d_in[9];
    float* out = (float*)d_out;

    cudaFuncSetAttribute(hmma_gemm, cudaFuncAttributeMaxDynamicSharedMemorySize, GSMEM);
    cudaFuncSetAttribute(attn_hmma, cudaFuncAttributeMaxDynamicSharedMemorySize, ASMEM);

    // 1. split x -> bf16 hi/lo
    split_x_kernel<<<(Mm * Dd / 4) / 256, 256>>>((const float4*)x);

    // 2. transpose + split weights
    {
        dim3 g(32, 32, 4), blk(32, 8);
        trans_split_w_kernel<<<g, blk>>>(wq, wk, wv, wo);
    }

    // 3. QKV projections (HMMA), writes bf16 hi/lo q/k/v
    {
        dim3 g(Dd / 128, Mm / 128, 3), blk(256);
        hmma_gemm<<<g, blk, GSMEM>>>(0, bq, bk, bv, nullptr);
    }

    // 4. Flash attention (HMMA), writes bf16 hi/lo attn output
    {
        dim3 g(Ss / 128, Bb * Hh), blk(256);
        attn_hmma<<<g, blk, ASMEM>>>();
    }

    // 5. Output projection (HMMA) -> fp32 out
    {
        dim3 g(Dd / 128, Mm / 128, 1), blk(256);
        hmma_gemm<<<g, blk, GSMEM>>>(1, bo, nullptr, nullptr, out);
    }
}